// round 4
// baseline (speedup 1.0000x reference)
#include <cuda_runtime.h>
#include <math.h>

#define BB 256
#define TT 256
#define DD 128
#define HH 512
#define G3 1536
#define G6 3072
#define NCTA 296
typedef unsigned long long ull;

__device__ float g_h[BB*HH];
__device__ float g_hp[BB*HH];
__device__ float g_gh0[BB*G3];
__device__ float g_g1[BB*G6];
__device__ float g_imp[BB*DD];
__device__ unsigned g_bar;

__global__ void init_kernel() {
    unsigned idx = blockIdx.x * blockDim.x + threadIdx.x;
    if (idx == 0) g_bar = 0u;
    for (unsigned i = idx; i < BB*HH; i += gridDim.x * blockDim.x) g_h[i] = 0.f;
}

__device__ __forceinline__ void grid_barrier(unsigned &target) {
    __syncthreads();
    target += gridDim.x;
    if (threadIdx.x == 0) {
        __threadfence();
        atomicAdd(&g_bar, 1u);
        int sp = 0;
        while (*((volatile unsigned*)&g_bar) < target)
            if (++sp > 256) __nanosleep(32);
    }
    __syncthreads();
}

__device__ __forceinline__ float sigf(float x){ return 1.f/(1.f+expf(-x)); }
__device__ __forceinline__ void unpack2(ull v, float &lo, float &hi){
    asm("mov.b64 {%0,%1},%2;" : "=f"(lo), "=f"(hi) : "l"(v));
}
__device__ __forceinline__ ull fma2(ull a, ull b, ull c){
    ull d; asm("fma.rn.f32x2 %0,%1,%2,%3;" : "=l"(d) : "l"(a), "l"(b), "l"(c)); return d;
}

// 64m x (16*ND) tile GEMM, 256 threads, micro 4m x ND via fma.rn.f32x2.
// A rows (state) via __ldcg, weights via __ldg. B stored DUPLICATED in smem
// (each value twice) so b operands load as f32x2 with no packing MOVs.
// As[buf][k][64], Bs[buf][k][XW]; KC=32, double buffered, 1 sync/chunk.
template<int KD, int ND, class AROW, class WROW, class EPI>
__device__ __forceinline__ void gemm(float* As, float* Bs, int m0,
                                     AROW arow, WROW wrow, EPI epi)
{
    constexpr int XW = (ND==2) ? 64 : 128;
    constexpr int NC = KD / 32;
    const int tid = threadIdx.x;
    const int ar = tid >> 2, af = (tid & 3) * 4;        // a loader: row, k-slot
    const int nrow0 = tid >> 3, f0 = (tid & 7) * 4;     // b loader slot 0
    const int nrow1 = (tid + 256) >> 3;                 // slot 1 (ND==3, tid<128)
    const bool has1 = (ND == 3) && (tid < 128);
    const int mg = tid >> 4, ng = tid & 15;

    const float* ap  = arow(m0 + ar);
    const float* wp0 = wrow(nrow0);
    const float* wp1 = has1 ? wrow(nrow1) : wp0;
    const int x0 = (ND==2) ? nrow0*2 : (nrow0/3)*8 + (nrow0%3)*2;
    const int x1 = (ND==2) ? 0       : (nrow1/3)*8 + (nrow1%3)*2;

    ull acc[2][ND];
    #pragma unroll
    for (int p = 0; p < 2; p++)
        #pragma unroll
        for (int d = 0; d < ND; d++) acc[p][d] = 0ull;

    float4 pa0 = __ldcg((const float4*)(ap + af));
    float4 pa1 = __ldcg((const float4*)(ap + 16 + af));
    float4 pb0 = __ldg ((const float4*)(wp0 + f0));
    float4 pb1 = pb0;
    if (has1) pb1 = __ldg((const float4*)(wp1 + f0));

    auto store = [&](int buf){
        float* A0 = As + buf * 2048;
        A0[(af+0)*64+ar]=pa0.x; A0[(af+1)*64+ar]=pa0.y; A0[(af+2)*64+ar]=pa0.z; A0[(af+3)*64+ar]=pa0.w;
        A0[(af+16)*64+ar]=pa1.x; A0[(af+17)*64+ar]=pa1.y; A0[(af+18)*64+ar]=pa1.z; A0[(af+19)*64+ar]=pa1.w;
        float* B0 = Bs + buf * 32 * XW;
        B0[(f0+0)*XW+x0]=pb0.x; B0[(f0+0)*XW+x0+1]=pb0.x;
        B0[(f0+1)*XW+x0]=pb0.y; B0[(f0+1)*XW+x0+1]=pb0.y;
        B0[(f0+2)*XW+x0]=pb0.z; B0[(f0+2)*XW+x0+1]=pb0.z;
        B0[(f0+3)*XW+x0]=pb0.w; B0[(f0+3)*XW+x0+1]=pb0.w;
        if (has1) {
            B0[(f0+0)*XW+x1]=pb1.x; B0[(f0+0)*XW+x1+1]=pb1.x;
            B0[(f0+1)*XW+x1]=pb1.y; B0[(f0+1)*XW+x1+1]=pb1.y;
            B0[(f0+2)*XW+x1]=pb1.z; B0[(f0+2)*XW+x1+1]=pb1.z;
            B0[(f0+3)*XW+x1]=pb1.w; B0[(f0+3)*XW+x1+1]=pb1.w;
        }
    };

    store(0);
    __syncthreads();

    for (int ch = 0; ch < NC; ch++) {
        if (ch + 1 < NC) {
            const int k = (ch + 1) * 32;
            pa0 = __ldcg((const float4*)(ap + k + af));
            pa1 = __ldcg((const float4*)(ap + k + 16 + af));
            pb0 = __ldg ((const float4*)(wp0 + k + f0));
            if (has1) pb1 = __ldg((const float4*)(wp1 + k + f0));
        }
        const float* Ac = As + (ch & 1) * 2048;
        const float* Bc = Bs + (ch & 1) * 32 * XW;
        #pragma unroll
        for (int kk = 0; kk < 32; kk++) {
            ull a0 = *(const ull*)(Ac + kk*64 + mg*4);
            ull a1 = *(const ull*)(Ac + kk*64 + mg*4 + 2);
            const float* br = Bc + kk*XW + ng*((ND==2)?4:8);
            ulonglong2 bb = *(const ulonglong2*)br;
            acc[0][0] = fma2(a0, bb.x, acc[0][0]);
            acc[1][0] = fma2(a1, bb.x, acc[1][0]);
            acc[0][1] = fma2(a0, bb.y, acc[0][1]);
            acc[1][1] = fma2(a1, bb.y, acc[1][1]);
            if (ND == 3) {
                ull b2 = *(const ull*)(br + 4);
                acc[0][2] = fma2(a0, b2, acc[0][2]);
                acc[1][2] = fma2(a1, b2, acc[1][2]);
            }
        }
        if (ch + 1 < NC) store((ch + 1) & 1);
        __syncthreads();
    }

    float c[4][ND];
    #pragma unroll
    for (int p = 0; p < 2; p++)
        #pragma unroll
        for (int d = 0; d < ND; d++)
            unpack2(acc[p][d], c[2*p][d], c[2*p+1][d]);
    epi(c, m0 + mg*4, ng);
}

__global__ void __launch_bounds__(256, 2) brits_kernel(
    const float* __restrict__ X,     const float* __restrict__ Msk,
    const float* __restrict__ W_ih0, const float* __restrict__ W_hh0,
    const float* __restrict__ b_ih0, const float* __restrict__ b_hh0,
    const float* __restrict__ W_ih1, const float* __restrict__ W_hh1,
    const float* __restrict__ b_ih1, const float* __restrict__ b_hh1,
    const float* __restrict__ W_out, const float* __restrict__ b_out,
    float* __restrict__ out)
{
    __shared__ __align__(16) float sm[12288];   // 48KB: As 4096 + Bs 8192
    float* As = sm;
    float* Bs = sm + 4096;

    float* pre_o = out;
    float* out_o = out + (size_t)BB*TT*DD;
    float* hf_o  = out + (size_t)2*BB*TT*DD;
    float* hid_o = hf_o + (size_t)BB*HH;

    unsigned target = 0;
    const int gs   = gridDim.x * blockDim.x;
    const int gtid = blockIdx.x * blockDim.x + threadIdx.x;
    const int bx   = blockIdx.x;

    for (int t = 0; t < TT; t++) {
        // ---- A: [gh0 | est] = h @ [W_hh0 ; W_out]^T ; imputation. 208 tiles 64x32.
        if (bx < 208) {
            const int m0 = (bx / 52) * 64, n0 = (bx % 52) * 32;
            auto arow = [](int m){ return g_h + (size_t)m * HH; };
            auto wrow = [&](int nr){
                int n = n0 + nr;
                return (n < G3) ? W_hh0 + (size_t)n*HH : W_out + (size_t)(n-G3)*HH;
            };
            auto epi = [&](float (&c)[4][2], int mb, int ngl){
                #pragma unroll
                for (int i = 0; i < 4; i++) {
                    int b = mb + i;
                    #pragma unroll
                    for (int d = 0; d < 2; d++) {
                        int n = n0 + ngl*2 + d; float v = c[i][d];
                        if (n < G3) g_gh0[b*G3 + n] = v + b_hh0[n];
                        else {
                            int dd = n - G3;
                            float est = v + b_out[dd];
                            int io = (b*TT + t)*DD + dd;
                            pre_o[io] = est;
                            float imp = est + Msk[io] * (X[io] - est);
                            g_imp[b*DD + dd] = imp;
                            if (t > 0) out_o[io - DD] = imp;
                        }
                    }
                }
            };
            gemm<HH, 2>(As, Bs, m0, arow, wrow, epi);
        }
        grid_barrier(target);

        // ---- B: fused cell-0: gi0 triple GEMM (K=128) + gate epilogue -> h'. 128 tiles 64m x 16j.
        if (bx < 128) {
            const int m0 = (bx >> 5) * 64, j0 = (bx & 31) * 16;
            auto arow = [](int m){ return g_imp + (size_t)m * DD; };
            auto wrow = [&](int nr){
                int row = j0 + nr/3 + HH*(nr%3);
                return W_ih0 + (size_t)row * DD;
            };
            auto epi = [&](float (&c)[4][3], int mb, int ngl){
                int j = j0 + ngl;
                #pragma unroll
                for (int i = 0; i < 4; i++) {
                    int b = mb + i, gb = b*G3 + j;
                    float gr = c[i][0] + b_ih0[j]        + __ldcg(&g_gh0[gb]);
                    float gz = c[i][1] + b_ih0[j + HH]   + __ldcg(&g_gh0[gb + HH]);
                    float gn = c[i][2] + b_ih0[j + 2*HH];
                    float hn = __ldcg(&g_gh0[gb + 2*HH]);
                    float r = sigf(gr), z = sigf(gz);
                    float nn = tanhf(gn + r * hn);
                    g_hp[b*HH + j] = (1.f - z) * nn + z * __ldcg(&g_h[b*HH + j]);
                }
            };
            gemm<DD, 3>(As, Bs, m0, arow, wrow, epi);
        }
        grid_barrier(target);

        // ---- C1: g1 = h' @ [W_ih1 ; W_hh1]^T. 256 tiles 64m x 48n.
        if (bx < 256) {
            const int m0 = (bx >> 6) * 64, n0c = (bx & 63) * 48;
            auto arow = [](int m){ return g_hp + (size_t)m * HH; };
            auto wrow = [&](int nr){
                int n = n0c + nr;
                return (n < G3) ? W_ih1 + (size_t)n*HH : W_hh1 + (size_t)(n-G3)*HH;
            };
            auto epi = [&](float (&c)[4][3], int mb, int ngl){
                #pragma unroll
                for (int i = 0; i < 4; i++)
                    #pragma unroll
                    for (int d = 0; d < 3; d++)
                        g_g1[(size_t)(mb+i)*G6 + n0c + ngl*3 + d] = c[i][d];
            };
            gemm<HH, 3>(As, Bs, m0, arow, wrow, epi);
        }
        grid_barrier(target);

        // ---- C2: cell-1 gates -> h ; emit hidden states
        for (int idx = gtid; idx < BB*HH; idx += gs) {
            int b = idx >> 9, j = idx & 511;
            int base = b*G6 + j;
            float ar2 = __ldcg(&g_g1[base])             + b_ih1[j]
                      + __ldcg(&g_g1[base + G3])        + b_hh1[j];
            float az  = __ldcg(&g_g1[base + HH])        + b_ih1[j + HH]
                      + __ldcg(&g_g1[base + G3 + HH])   + b_hh1[j + HH];
            float an  = __ldcg(&g_g1[base + 2*HH])      + b_ih1[j + 2*HH];
            float hn  = __ldcg(&g_g1[base + G3 + 2*HH]) + b_hh1[j + 2*HH];
            float r = sigf(ar2), z = sigf(az);
            float nn = tanhf(an + r * hn);
            float hnew = (1.f - z) * nn + z * __ldcg(&g_hp[idx]);
            g_h[idx] = hnew;
            hid_o[((size_t)b*TT + t)*HH + j] = hnew;
        }
        grid_barrier(target);
    }

    // ---- final est(h_final) -> output_collector[:, T-1, :] ; h_final copy
    for (int idx = gtid; idx < BB*DD; idx += gs) {
        int b = idx >> 7, d = idx & 127;
        const float4* hv = (const float4*)(g_h + (size_t)b*HH);
        const float4* wv = (const float4*)(W_out + (size_t)d*HH);
        float s = b_out[d];
        #pragma unroll 8
        for (int q = 0; q < HH/4; q++) {
            float4 a = __ldcg(&hv[q]); float4 w = __ldg(&wv[q]);
            s += a.x*w.x + a.y*w.y + a.z*w.z + a.w*w.w;
        }
        out_o[((size_t)b*TT + (TT-1))*DD + d] = s;
    }
    for (int idx = gtid; idx < BB*HH; idx += gs)
        hf_o[idx] = __ldcg(&g_h[idx]);
}

extern "C" void kernel_launch(void* const* d_in, const int* in_sizes, int n_in,
                              void* d_out, int out_size) {
    const float* X     = (const float*)d_in[0];
    const float* Msk   = (const float*)d_in[1];
    const float* W_ih0 = (const float*)d_in[2];
    const float* W_hh0 = (const float*)d_in[3];
    const float* b_ih0 = (const float*)d_in[4];
    const float* b_hh0 = (const float*)d_in[5];
    const float* W_ih1 = (const float*)d_in[6];
    const float* W_hh1 = (const float*)d_in[7];
    const float* b_ih1 = (const float*)d_in[8];
    const float* b_hh1 = (const float*)d_in[9];
    const float* W_out = (const float*)d_in[10];
    const float* b_out = (const float*)d_in[11];

    init_kernel<<<64, 256>>>();
    brits_kernel<<<NCTA, 256>>>(X, Msk, W_ih0, W_hh0, b_ih0, b_hh0,
                                W_ih1, W_hh1, b_ih1, b_hh1, W_out, b_out, (float*)d_out);
}

// round 6
// speedup vs baseline: 4.4292x; 4.4292x over previous
#include <cuda_runtime.h>
#include <cuda_bf16.h>
#include <math.h>
#include <stdint.h>

#define BB 256
#define TT 256
#define DD 128
#define HH 512
#define G3 1536
#define NCTA 148
typedef unsigned u32;
typedef __nv_bfloat16 bf;

// persistent state
__device__ float g_h[BB*HH];
__device__ float g_hp[BB*HH];
__device__ float g_gh0[BB*G3];
__device__ bf g_h_hi[BB*HH],  g_h_lo[BB*HH];
__device__ bf g_hp_hi[BB*HH], g_hp_lo[BB*HH];
__device__ bf g_imp_hi[BB*DD], g_imp_lo[BB*DD];
__device__ unsigned g_bar;
// pre-split weights
__device__ bf wA_hi[1664*HH], wA_lo[1664*HH];  // [W_hh0 ; W_out]
__device__ bf wB_hi[G3*DD],   wB_lo[G3*DD];    // W_ih0, gate-blocked by 8
__device__ bf wC_hi[3072*HH], wC_lo[3072*HH];  // [W_ih1;W_hh1], 6-gate blocks of 8

__device__ __forceinline__ void splitw(float x, bf* hi, bf* lo){
    bf h = __float2bfloat16(x);
    *hi = h; *lo = __float2bfloat16(x - __bfloat162float(h));
}

__global__ void init_kernel(const float* W_ih0, const float* W_hh0,
                            const float* W_ih1, const float* W_hh1,
                            const float* W_out){
    int idx = blockIdx.x*blockDim.x + threadIdx.x;
    int gs  = gridDim.x*blockDim.x;
    if (idx == 0) g_bar = 0u;
    for (int i = idx; i < BB*HH; i += gs){
        g_h[i] = 0.f; g_h_hi[i] = __float2bfloat16(0.f); g_h_lo[i] = __float2bfloat16(0.f);
    }
    for (int i = idx; i < 1664*HH; i += gs){
        int n = i/HH, k = i - n*HH;
        float x = (n < G3) ? W_hh0[(size_t)n*HH + k] : W_out[(size_t)(n-G3)*HH + k];
        splitw(x, &wA_hi[i], &wA_lo[i]);
    }
    for (int i = idx; i < G3*DD; i += gs){
        int q = i/DD, k = i - q*DD;
        int gi = q/24, w = q%24, gate = w>>3, j = gi*8 + (w&7);
        splitw(W_ih0[(size_t)(gate*HH + j)*DD + k], &wB_hi[i], &wB_lo[i]);
    }
    for (int i = idx; i < 3072*HH; i += gs){
        int q = i/HH, k = i - q*HH;
        int gi = q/48, w = q%48, gate = w>>3, j = gi*8 + (w&7);
        float x = (gate < 3) ? W_ih1[(size_t)(gate*HH + j)*HH + k]
                             : W_hh1[(size_t)((gate-3)*HH + j)*HH + k];
        splitw(x, &wC_hi[i], &wC_lo[i]);
    }
}

// ---- helpers ----
__device__ __forceinline__ u32 s2u(const void* p){
    u32 a; asm("{ .reg .u64 t; cvta.to.shared.u64 t, %1; cvt.u32.u64 %0, t; }" : "=r"(a) : "l"(p));
    return a;
}
__device__ __forceinline__ void cpasync16(u32 dst, const void* src){
    asm volatile("cp.async.cg.shared.global [%0], [%1], 16;" :: "r"(dst), "l"(src));
}
#define CP_COMMIT() asm volatile("cp.async.commit_group;" ::: "memory")
#define CP_WAIT1()  asm volatile("cp.async.wait_group 1;" ::: "memory")
#define CP_WAIT0()  asm volatile("cp.async.wait_group 0;" ::: "memory")

__device__ __forceinline__ void mma_bf(float* d, u32 a0,u32 a1,u32 a2,u32 a3, u32 b0,u32 b1){
    asm volatile("mma.sync.aligned.m16n8k16.row.col.f32.bf16.bf16.f32 "
        "{%0,%1,%2,%3},{%4,%5,%6,%7},{%8,%9},{%0,%1,%2,%3};"
        : "+f"(d[0]),"+f"(d[1]),"+f"(d[2]),"+f"(d[3])
        : "r"(a0),"r"(a1),"r"(a2),"r"(a3),"r"(b0),"r"(b1));
}

__device__ __forceinline__ void grid_barrier(unsigned &target){
    __syncthreads();
    target += gridDim.x;
    if (threadIdx.x == 0){
        __threadfence();
        atomicAdd(&g_bar, 1u);
        int sp = 0;
        while (*((volatile unsigned*)&g_bar) < target)
            if (++sp > 256) __nanosleep(32);
    }
    __syncthreads();
}
__device__ __forceinline__ float sigf(float x){ return 1.f/(1.f+expf(-x)); }

// smem buffer layout (bytes), rows padded to 144B (72 bf16) for conflict-free frag loads
#define A_HI 0
#define A_LO 18432
#define B_HI 36864
#define B_LO 43776
#define BUFSZ 50688
#define SMEMSZ (2*BUFSZ)

extern __shared__ __align__(16) char smc[];

template<int NR>
__device__ __forceinline__ void load_chunk(int buf,
    const bf* Ahi, const bf* Alo, int Alda,
    const bf* Bhi, const bf* Blo, int Blda, int kc)
{
    const int tid = threadIdx.x;
    const u32 sb = s2u(smc) + buf*BUFSZ;
    #pragma unroll
    for (int i = 0; i < 4; i++){
        int seg = tid + i*256;             // 1024 segs: 128 rows x 8
        int r = seg >> 3, c = seg & 7;
        u32 d = sb + r*144 + c*16;
        cpasync16(d + A_HI, Ahi + (size_t)r*Alda + kc + c*8);
        cpasync16(d + A_LO, Alo + (size_t)r*Alda + kc + c*8);
    }
    for (int seg = tid; seg < NR*8; seg += 256){
        int r = seg >> 3, c = seg & 7;
        u32 d = sb + B_HI + r*144 + c*16;
        cpasync16(d,                 Bhi + (size_t)r*Blda + kc + c*8);
        cpasync16(d + (B_LO - B_HI), Blo + (size_t)r*Blda + kc + c*8);
    }
}

template<int MFR,int NFR>
__device__ __forceinline__ void mma_chunk(int buf, int wm, int wn, float (*acc)[NFR][4])
{
    const int lane = threadIdx.x & 31;
    const int g = lane >> 2, t = lane & 3;
    const char* base = smc + buf*BUFSZ;
    #pragma unroll
    for (int k16 = 0; k16 < 4; k16++){
        const int kb = k16*32 + 4*t;       // byte offset of k = 16*k16 + 2t
        u32 ah[MFR][4], al[MFR][4];
        #pragma unroll
        for (int f = 0; f < MFR; f++){
            const char* r0 = base + A_HI + (wm + 16*f + g)*144 + kb;
            const char* r1 = r0 + 8*144;
            ah[f][0] = *(const u32*)r0;      ah[f][1] = *(const u32*)r1;
            ah[f][2] = *(const u32*)(r0+16); ah[f][3] = *(const u32*)(r1+16);
            const char* l0 = r0 + (A_LO - A_HI);
            const char* l1 = r1 + (A_LO - A_HI);
            al[f][0] = *(const u32*)l0;      al[f][1] = *(const u32*)l1;
            al[f][2] = *(const u32*)(l0+16); al[f][3] = *(const u32*)(l1+16);
        }
        #pragma unroll
        for (int nf = 0; nf < NFR; nf++){
            const char* rb = base + B_HI + (wn + 8*nf + g)*144 + kb;
            u32 bh0 = *(const u32*)rb,          bh1 = *(const u32*)(rb+16);
            u32 bl0 = *(const u32*)(rb+6912),   bl1 = *(const u32*)(rb+6912+16);
            #pragma unroll
            for (int f = 0; f < MFR; f++){
                mma_bf(acc[f][nf], ah[f][0],ah[f][1],ah[f][2],ah[f][3], bh0,bh1);
                mma_bf(acc[f][nf], ah[f][0],ah[f][1],ah[f][2],ah[f][3], bl0,bl1);
                mma_bf(acc[f][nf], al[f][0],al[f][1],al[f][2],al[f][3], bh0,bh1);
            }
        }
    }
}

template<int KD,int NR,int MFR,int NFR>
__device__ __forceinline__ void gemm_run(int wm, int wn, float (*acc)[NFR][4],
    const bf* Ahi, const bf* Alo, int Alda, const bf* Bhi, const bf* Blo)
{
    constexpr int NC = KD / 64;
    #pragma unroll
    for (int f = 0; f < MFR; f++)
        #pragma unroll
        for (int n = 0; n < NFR; n++)
            #pragma unroll
            for (int q = 0; q < 4; q++) acc[f][n][q] = 0.f;

    load_chunk<NR>(0, Ahi, Alo, Alda, Bhi, Blo, KD, 0);
    CP_COMMIT();
    for (int ch = 0; ch < NC; ch++){
        if (ch + 1 < NC){
            load_chunk<NR>((ch+1)&1, Ahi, Alo, Alda, Bhi, Blo, KD, (ch+1)*64);
            CP_COMMIT(); CP_WAIT1();
        } else CP_WAIT0();
        __syncthreads();
        mma_chunk<MFR,NFR>(ch&1, wm, wn, acc);
        __syncthreads();
    }
}

__global__ void __launch_bounds__(256, 1) brits_kernel(
    const float* __restrict__ X,     const float* __restrict__ Msk,
    const float* __restrict__ b_ih0, const float* __restrict__ b_hh0,
    const float* __restrict__ b_ih1, const float* __restrict__ b_hh1,
    const float* __restrict__ W_out, const float* __restrict__ b_out,
    float* __restrict__ out)
{
    const int tid = threadIdx.x, wid = tid >> 5, lane = tid & 31, bx = blockIdx.x;
    const int g = lane >> 2, t = lane & 3;

    float* pre_o = out;
    float* out_o = out + (size_t)BB*TT*DD;
    float* hf_o  = out + (size_t)2*BB*TT*DD;
    float* hid_o = hf_o + (size_t)BB*HH;

    unsigned target = 0;
    const int gs   = gridDim.x * blockDim.x;
    const int gtid = bx * blockDim.x + tid;

    for (int ts = 0; ts < TT; ts++){
        // ---- A: [gh0 | est] = h @ [W_hh0;W_out]^T ; imputation. 104 CTAs 128x32
        if (bx < 104){
            const int m0 = (bx & 1) * 128, n0 = (bx >> 1) * 32;
            const int wm = (wid & 3) * 32, wn = (wid >> 2) * 16;
            float acc[2][2][4];
            gemm_run<512,32,2,2>(wm, wn, acc,
                g_h_hi + (size_t)m0*HH, g_h_lo + (size_t)m0*HH, HH,
                wA_hi + (size_t)n0*HH, wA_lo + (size_t)n0*HH);
            #pragma unroll
            for (int f = 0; f < 2; f++)
                #pragma unroll
                for (int nf = 0; nf < 2; nf++)
                    #pragma unroll
                    for (int rh = 0; rh < 2; rh++)
                        #pragma unroll
                        for (int d = 0; d < 2; d++){
                            int m = m0 + wm + 16*f + g + 8*rh;
                            int n = n0 + wn + 8*nf + 2*t + d;
                            float v = acc[f][nf][rh*2 + d];
                            if (n < G3) g_gh0[m*G3 + n] = v + b_hh0[n];
                            else {
                                int dd = n - G3;
                                float est = v + b_out[dd];
                                int io = (m*TT + ts)*DD + dd;
                                pre_o[io] = est;
                                float imp = est + Msk[io] * (X[io] - est);
                                bf hi = __float2bfloat16(imp);
                                g_imp_hi[m*DD + dd] = hi;
                                g_imp_lo[m*DD + dd] = __float2bfloat16(imp - __bfloat162float(hi));
                                if (ts > 0) out_o[io - DD] = imp;
                            }
                        }
        }
        grid_barrier(target);

        // ---- B: fused cell-0. 128 CTAs 128x24 (gate-blocked), K=128
        if (bx < 128){
            const int m0 = (bx & 1) * 128, q0 = (bx >> 1) * 24, j0 = (bx >> 1) * 8;
            const int wm = wid * 16;
            float acc[1][3][4];
            gemm_run<128,24,1,3>(wm, 0, acc,
                g_imp_hi + (size_t)m0*DD, g_imp_lo + (size_t)m0*DD, DD,
                wB_hi + (size_t)q0*DD, wB_lo + (size_t)q0*DD);
            #pragma unroll
            for (int rh = 0; rh < 2; rh++)
                #pragma unroll
                for (int d = 0; d < 2; d++){
                    int m = m0 + wm + g + 8*rh;
                    int j = j0 + 2*t + d;
                    int q = rh*2 + d;
                    float gr = acc[0][0][q] + b_ih0[j]      + __ldcg(&g_gh0[m*G3 + j]);
                    float gz = acc[0][1][q] + b_ih0[HH + j] + __ldcg(&g_gh0[m*G3 + HH + j]);
                    float gn = acc[0][2][q] + b_ih0[2*HH + j];
                    float hn = __ldcg(&g_gh0[m*G3 + 2*HH + j]);
                    float r = sigf(gr), z = sigf(gz);
                    float nn = tanhf(gn + r * hn);
                    float hp = (1.f - z) * nn + z * __ldcg(&g_h[m*HH + j]);
                    g_hp[m*HH + j] = hp;
                    bf hi = __float2bfloat16(hp);
                    g_hp_hi[m*HH + j] = hi;
                    g_hp_lo[m*HH + j] = __float2bfloat16(hp - __bfloat162float(hi));
                }
        }
        grid_barrier(target);

        // ---- C: fused cell-1. 128 CTAs 128x48 (6-gate blocks), K=512
        if (bx < 128){
            const int m0 = (bx & 1) * 128, q0 = (bx >> 1) * 48, j0 = (bx >> 1) * 8;
            const int wm = wid * 16;
            float acc[1][6][4];
            gemm_run<512,48,1,6>(wm, 0, acc,
                g_hp_hi + (size_t)m0*HH, g_hp_lo + (size_t)m0*HH, HH,
                wC_hi + (size_t)q0*HH, wC_lo + (size_t)q0*HH);
            #pragma unroll
            for (int rh = 0; rh < 2; rh++)
                #pragma unroll
                for (int d = 0; d < 2; d++){
                    int m = m0 + wm + g + 8*rh;
                    int j = j0 + 2*t + d;
                    int q = rh*2 + d;
                    float r = sigf(acc[0][0][q] + b_ih1[j] + acc[0][3][q] + b_hh1[j]);
                    float z = sigf(acc[0][1][q] + b_ih1[HH+j] + acc[0][4][q] + b_hh1[HH+j]);
                    float nn = tanhf(acc[0][2][q] + b_ih1[2*HH+j]
                                     + r * (acc[0][5][q] + b_hh1[2*HH+j]));
                    float hnew = (1.f - z) * nn + z * __ldcg(&g_hp[m*HH + j]);
                    g_h[m*HH + j] = hnew;
                    bf hi = __float2bfloat16(hnew);
                    g_h_hi[m*HH + j] = hi;
                    g_h_lo[m*HH + j] = __float2bfloat16(hnew - __bfloat162float(hi));
                    hid_o[((size_t)m*TT + ts)*HH + j] = hnew;
                }
        }
        grid_barrier(target);
    }

    // tail: est(h_final) -> out_o[:, T-1, :] ; h_final copy
    for (int idx = gtid; idx < BB*DD; idx += gs){
        int b = idx >> 7, d = idx & 127;
        const float4* hv = (const float4*)(g_h + (size_t)b*HH);
        const float4* wv = (const float4*)(W_out + (size_t)d*HH);
        float s = b_out[d];
        #pragma unroll 8
        for (int q = 0; q < HH/4; q++){
            float4 a = __ldcg(&hv[q]); float4 w = __ldg(&wv[q]);
            s += a.x*w.x + a.y*w.y + a.z*w.z + a.w*w.w;
        }
        out_o[((size_t)b*TT + (TT-1))*DD + d] = s;
    }
    for (int idx = gtid; idx < BB*HH; idx += gs)
        hf_o[idx] = __ldcg(&g_h[idx]);
}

extern "C" void kernel_launch(void* const* d_in, const int* in_sizes, int n_in,
                              void* d_out, int out_size) {
    const float* X     = (const float*)d_in[0];
    const float* Msk   = (const float*)d_in[1];
    const float* W_ih0 = (const float*)d_in[2];
    const float* W_hh0 = (const float*)d_in[3];
    const float* b_ih0 = (const float*)d_in[4];
    const float* b_hh0 = (const float*)d_in[5];
    const float* W_ih1 = (const float*)d_in[6];
    const float* W_hh1 = (const float*)d_in[7];
    const float* b_ih1 = (const float*)d_in[8];
    const float* b_hh1 = (const float*)d_in[9];
    const float* W_out = (const float*)d_in[10];
    const float* b_out = (const float*)d_in[11];

    static bool attr_set = false;
    if (!attr_set){
        cudaFuncSetAttribute(brits_kernel, cudaFuncAttributeMaxDynamicSharedMemorySize, SMEMSZ);
        attr_set = true;
    }
    init_kernel<<<512, 256>>>(W_ih0, W_hh0, W_ih1, W_hh1, W_out);
    brits_kernel<<<NCTA, 256, SMEMSZ>>>(X, Msk, b_ih0, b_hh0, b_ih1, b_hh1,
                                        W_out, b_out, (float*)d_out);
}

// round 7
// speedup vs baseline: 4.4651x; 1.0081x over previous
#include <cuda_runtime.h>
#include <cuda_bf16.h>
#include <math.h>
#include <stdint.h>

#define BB 256
#define TT 256
#define DD 128
#define HH 512
#define G3 1536
#define NCTA 148
typedef unsigned u32;
typedef __nv_bfloat16 bf;

// persistent state
__device__ float g_h[BB*HH];
__device__ float g_hp[BB*HH];
__device__ float g_gh0[BB*G3];
__device__ bf g_h_hi[BB*HH],  g_h_lo[BB*HH];
__device__ bf g_hp_hi[BB*HH], g_hp_lo[BB*HH];
__device__ bf g_imp_hi[BB*DD], g_imp_lo[BB*DD];
__device__ unsigned g_bar;
// pre-split weights
__device__ bf wA_hi[1664*HH], wA_lo[1664*HH];  // [W_hh0 ; W_out]
__device__ bf wB_hi[G3*DD],   wB_lo[G3*DD];    // W_ih0 gate-blocked by 8
__device__ bf wC_hi[3072*HH], wC_lo[3072*HH];  // [W_ih1;W_hh1] 6-gate blocks of 8

__device__ __forceinline__ void splitw(float x, bf* hi, bf* lo){
    bf h = __float2bfloat16(x);
    *hi = h; *lo = __float2bfloat16(x - __bfloat162float(h));
}

__global__ void init_kernel(const float* W_ih0, const float* W_hh0,
                            const float* W_ih1, const float* W_hh1,
                            const float* W_out){
    int idx = blockIdx.x*blockDim.x + threadIdx.x;
    int gs  = gridDim.x*blockDim.x;
    if (idx == 0) g_bar = 0u;
    for (int i = idx; i < BB*HH; i += gs){
        g_h[i] = 0.f; g_h_hi[i] = __float2bfloat16(0.f); g_h_lo[i] = __float2bfloat16(0.f);
    }
    for (int i = idx; i < 1664*HH; i += gs){
        int n = i/HH, k = i - n*HH;
        float x = (n < G3) ? W_hh0[(size_t)n*HH + k] : W_out[(size_t)(n-G3)*HH + k];
        splitw(x, &wA_hi[i], &wA_lo[i]);
    }
    for (int i = idx; i < G3*DD; i += gs){
        int q = i/DD, k = i - q*DD;
        int gi = q/24, w = q%24, gate = w>>3, j = gi*8 + (w&7);
        splitw(W_ih0[(size_t)(gate*HH + j)*DD + k], &wB_hi[i], &wB_lo[i]);
    }
    for (int i = idx; i < 3072*HH; i += gs){
        int q = i/HH, k = i - q*HH;
        int gi = q/48, w = q%48, gate = w>>3, j = gi*8 + (w&7);
        float x = (gate < 3) ? W_ih1[(size_t)(gate*HH + j)*HH + k]
                             : W_hh1[(size_t)((gate-3)*HH + j)*HH + k];
        splitw(x, &wC_hi[i], &wC_lo[i]);
    }
}

// ---- helpers ----
__device__ __forceinline__ u32 s2u(const void* p){
    u32 a; asm("{ .reg .u64 t; cvta.to.shared.u64 t, %1; cvt.u32.u64 %0, t; }" : "=r"(a) : "l"(p));
    return a;
}
__device__ __forceinline__ void cpasync16(u32 dst, const void* src){
    asm volatile("cp.async.cg.shared.global [%0], [%1], 16;" :: "r"(dst), "l"(src));
}
#define CP_COMMIT() asm volatile("cp.async.commit_group;" ::: "memory")
#define CP_WAIT0()  asm volatile("cp.async.wait_group 0;" ::: "memory")

__device__ __forceinline__ void mma_bf(float* d, u32 a0,u32 a1,u32 a2,u32 a3, u32 b0,u32 b1){
    asm volatile("mma.sync.aligned.m16n8k16.row.col.f32.bf16.bf16.f32 "
        "{%0,%1,%2,%3},{%4,%5,%6,%7},{%8,%9},{%0,%1,%2,%3};"
        : "+f"(d[0]),"+f"(d[1]),"+f"(d[2]),"+f"(d[3])
        : "r"(a0),"r"(a1),"r"(a2),"r"(a3),"r"(b0),"r"(b1));
}

__device__ __forceinline__ void grid_barrier(unsigned &target){
    __syncthreads();
    target += gridDim.x;
    if (threadIdx.x == 0){
        __threadfence();
        atomicAdd(&g_bar, 1u);
        int sp = 0;
        while (*((volatile unsigned*)&g_bar) < target)
            if (++sp > 256) __nanosleep(32);
    }
    __syncthreads();
}
__device__ __forceinline__ float sigf(float x){ return 1.f/(1.f+expf(-x)); }

// ---- smem map (bytes). rows are 144B (64 bf16 data + pad) -> conflict-free 16B columns
#define WHA_OFF 0u              /* [8][32][144] = 36864 */
#define WHB_HI  36864u          /* [2][24][144] = 6912  */
#define WHB_LO  43776u          /* 6912 */
#define WHC_OFF 50688u          /* [8][48][144] = 55296 */
#define BUF0    105984u
#define BUF_SZ  43776u          /* AH 18432 | AL 18432 | WL 6912 */
#define AH_OFF  0u
#define AL_OFF  18432u
#define WL_OFF  36864u
#define SMEMSZ  (105984 + 2*43776)

extern __shared__ __align__(16) char smc[];

// stream one K64 chunk: A hi/lo always; W_lo only when !WRES
template<int NR, bool WRES>
__device__ __forceinline__ void load_chunk(int buf, const bf* Ahi, const bf* Alo, int lda,
                                           const bf* Wlo, int KW, int kc)
{
    const int tid = threadIdx.x;
    const u32 b = s2u(smc) + BUF0 + (u32)buf*BUF_SZ;
    #pragma unroll
    for (int i = 0; i < 4; i++){
        int seg = tid + i*256;             // 1024: 128 rows x 8
        int r = seg >> 3, c = seg & 7;
        u32 d = b + r*144 + c*16;
        cpasync16(d + AH_OFF, Ahi + (size_t)r*lda + kc + c*8);
        cpasync16(d + AL_OFF, Alo + (size_t)r*lda + kc + c*8);
    }
    if (!WRES){
        for (int seg = tid; seg < NR*8; seg += 256){
            int r = seg >> 3, c = seg & 7;
            cpasync16(b + WL_OFF + r*144 + c*16, Wlo + (size_t)r*KW + kc + c*8);
        }
    }
}

template<int MFR, int NFR>
__device__ __forceinline__ void mma_chunk(const char* Abh, const char* Abl,
                                          const char* Wh, const char* Wl,
                                          int wm, int wn, float (*acc)[NFR][4])
{
    const int lane = threadIdx.x & 31;
    const int g = lane >> 2, t = lane & 3;
    #pragma unroll
    for (int k16 = 0; k16 < 4; k16++){
        const int kb = k16*32 + 4*t;
        u32 ah[MFR][4], al[MFR][4];
        #pragma unroll
        for (int f = 0; f < MFR; f++){
            const char* r0 = Abh + (wm + 16*f + g)*144 + kb;
            const char* r1 = r0 + 8*144;
            ah[f][0] = *(const u32*)r0;      ah[f][1] = *(const u32*)r1;
            ah[f][2] = *(const u32*)(r0+16); ah[f][3] = *(const u32*)(r1+16);
            const char* l0 = Abl + (wm + 16*f + g)*144 + kb;
            const char* l1 = l0 + 8*144;
            al[f][0] = *(const u32*)l0;      al[f][1] = *(const u32*)l1;
            al[f][2] = *(const u32*)(l0+16); al[f][3] = *(const u32*)(l1+16);
        }
        #pragma unroll
        for (int nf = 0; nf < NFR; nf++){
            const char* rh = Wh + (wn + 8*nf + g)*144 + kb;
            const char* rl = Wl + (wn + 8*nf + g)*144 + kb;
            u32 bh0 = *(const u32*)rh, bh1 = *(const u32*)(rh+16);
            u32 bl0 = *(const u32*)rl, bl1 = *(const u32*)(rl+16);
            #pragma unroll
            for (int f = 0; f < MFR; f++){
                mma_bf(acc[f][nf], ah[f][0],ah[f][1],ah[f][2],ah[f][3], bh0,bh1);
                mma_bf(acc[f][nf], ah[f][0],ah[f][1],ah[f][2],ah[f][3], bl0,bl1);
                mma_bf(acc[f][nf], al[f][0],al[f][1],al[f][2],al[f][3], bh0,bh1);
            }
        }
    }
}

template<int NC, int NR, int MFR, int NFR, bool WRES>
__device__ __forceinline__ void gemm_run(u32 whiOff, u32 wloResOff,
    const bf* Wlo, int KW, const bf* Ahi, const bf* Alo, int lda,
    int wm, int wn, float (*acc)[NFR][4])
{
    #pragma unroll
    for (int f = 0; f < MFR; f++)
        #pragma unroll
        for (int n = 0; n < NFR; n++)
            #pragma unroll
            for (int q = 0; q < 4; q++) acc[f][n][q] = 0.f;

    load_chunk<NR,WRES>(0, Ahi, Alo, lda, Wlo, KW, 0);
    CP_COMMIT();
    for (int ch = 0; ch < NC; ch++){
        CP_WAIT0();
        __syncthreads();
        if (ch + 1 < NC){
            load_chunk<NR,WRES>((ch+1)&1, Ahi, Alo, lda, Wlo, KW, (ch+1)*64);
            CP_COMMIT();
        }
        const char* bufc = smc + BUF0 + (ch&1)*BUF_SZ;
        mma_chunk<MFR,NFR>(bufc + AH_OFF, bufc + AL_OFF,
                           smc + whiOff + (u32)ch*NR*144,
                           WRES ? (smc + wloResOff + (u32)ch*NR*144) : (bufc + WL_OFF),
                           wm, wn, acc);
        __syncthreads();
    }
}

__global__ void __launch_bounds__(256, 1) brits_kernel(
    const float* __restrict__ X,     const float* __restrict__ Msk,
    const float* __restrict__ b_ih0, const float* __restrict__ b_hh0,
    const float* __restrict__ b_ih1, const float* __restrict__ b_hh1,
    const float* __restrict__ W_out, const float* __restrict__ b_out,
    float* __restrict__ out)
{
    const int tid = threadIdx.x, wid = tid >> 5, lane = tid & 31, bx = blockIdx.x;
    const int g = lane >> 2, t = lane & 3;

    // ---- preload resident weights for this CTA's fixed tiles ----
    {
        const int nA = (bx >> 1) * 32;   // phase A tile (valid when bx<104)
        const int qB = (bx >> 1) * 24;   // phase B
        const int qC = (bx >> 1) * 48;   // phase C
        if (bx < 104)
            for (int s = tid; s < 8*32*8; s += 256){
                int ch = s >> 8, r = (s >> 3) & 31, c = s & 7;
                *(uint4*)(smc + WHA_OFF + (ch*32 + r)*144 + c*16) =
                    __ldg((const uint4*)(wA_hi + (size_t)(nA + r)*HH + ch*64 + c*8));
            }
        if (bx < 128){
            for (int s = tid; s < 2*24*8; s += 256){
                int ch = s / 192, r = (s >> 3) % 24, c = s & 7;
                *(uint4*)(smc + WHB_HI + (ch*24 + r)*144 + c*16) =
                    __ldg((const uint4*)(wB_hi + (size_t)(qB + r)*DD + ch*64 + c*8));
                *(uint4*)(smc + WHB_LO + (ch*24 + r)*144 + c*16) =
                    __ldg((const uint4*)(wB_lo + (size_t)(qB + r)*DD + ch*64 + c*8));
            }
            for (int s = tid; s < 8*48*8; s += 256){
                int ch = s / 384, r = (s >> 3) % 48, c = s & 7;
                *(uint4*)(smc + WHC_OFF + (ch*48 + r)*144 + c*16) =
                    __ldg((const uint4*)(wC_hi + (size_t)(qC + r)*HH + ch*64 + c*8));
            }
        }
        __syncthreads();
    }

    float* pre_o = out;
    float* out_o = out + (size_t)BB*TT*DD;
    float* hf_o  = out + (size_t)2*BB*TT*DD;
    float* hid_o = hf_o + (size_t)BB*HH;

    unsigned target = 0;
    const int gs   = gridDim.x * blockDim.x;
    const int gtid = bx * blockDim.x + tid;

    for (int ts = 0; ts < TT; ts++){
        // ---- A: [gh0 | est] = h @ [W_hh0;W_out]^T ; imputation. 104 CTAs 128x32
        if (bx < 104){
            const int m0 = (bx & 1) * 128, n0 = (bx >> 1) * 32;
            const int wm = (wid & 3) * 32, wn = (wid >> 2) * 16;
            float acc[2][2][4];
            gemm_run<8,32,2,2,false>(WHA_OFF, 0u, wA_lo + (size_t)n0*HH, HH,
                g_h_hi + (size_t)m0*HH, g_h_lo + (size_t)m0*HH, HH, wm, wn, acc);
            #pragma unroll
            for (int f = 0; f < 2; f++)
                #pragma unroll
                for (int nf = 0; nf < 2; nf++)
                    #pragma unroll
                    for (int rh = 0; rh < 2; rh++)
                        #pragma unroll
                        for (int d = 0; d < 2; d++){
                            int m = m0 + wm + 16*f + g + 8*rh;
                            int n = n0 + wn + 8*nf + 2*t + d;
                            float v = acc[f][nf][rh*2 + d];
                            if (n < G3) g_gh0[m*G3 + n] = v + b_hh0[n];
                            else {
                                int dd = n - G3;
                                float est = v + b_out[dd];
                                int io = (m*TT + ts)*DD + dd;
                                pre_o[io] = est;
                                float imp = est + Msk[io] * (X[io] - est);
                                bf hi = __float2bfloat16(imp);
                                g_imp_hi[m*DD + dd] = hi;
                                g_imp_lo[m*DD + dd] = __float2bfloat16(imp - __bfloat162float(hi));
                                if (ts > 0) out_o[io - DD] = imp;
                            }
                        }
        }
        grid_barrier(target);

        // ---- B: fused cell-0. 128 CTAs 128x24 (gate-blocked), K=128
        if (bx < 128){
            const int m0 = (bx & 1) * 128, j0 = (bx >> 1) * 8;
            const int wm = wid * 16;
            float acc[1][3][4];
            gemm_run<2,24,1,3,true>(WHB_HI, WHB_LO, (const bf*)0, DD,
                g_imp_hi + (size_t)m0*DD, g_imp_lo + (size_t)m0*DD, DD, wm, 0, acc);
            #pragma unroll
            for (int rh = 0; rh < 2; rh++)
                #pragma unroll
                for (int d = 0; d < 2; d++){
                    int m = m0 + wm + g + 8*rh;
                    int j = j0 + 2*t + d;
                    int q = rh*2 + d;
                    float gr = acc[0][0][q] + b_ih0[j]      + __ldcg(&g_gh0[m*G3 + j]);
                    float gz = acc[0][1][q] + b_ih0[HH + j] + __ldcg(&g_gh0[m*G3 + HH + j]);
                    float gn = acc[0][2][q] + b_ih0[2*HH + j];
                    float hn = __ldcg(&g_gh0[m*G3 + 2*HH + j]);
                    float r = sigf(gr), z = sigf(gz);
                    float nn = tanhf(gn + r * hn);
                    float hp = (1.f - z) * nn + z * __ldcg(&g_h[m*HH + j]);
                    g_hp[m*HH + j] = hp;
                    bf hi = __float2bfloat16(hp);
                    g_hp_hi[m*HH + j] = hi;
                    g_hp_lo[m*HH + j] = __float2bfloat16(hp - __bfloat162float(hi));
                }
        }
        grid_barrier(target);

        // ---- C: fused cell-1. 128 CTAs 128x48 (6-gate blocks), K=512
        if (bx < 128){
            const int m0 = (bx & 1) * 128, q0 = (bx >> 1) * 48, j0 = (bx >> 1) * 8;
            const int wm = wid * 16;
            float acc[1][6][4];
            gemm_run<8,48,1,6,false>(WHC_OFF, 0u, wC_lo + (size_t)q0*HH, HH,
                g_hp_hi + (size_t)m0*HH, g_hp_lo + (size_t)m0*HH, HH, wm, 0, acc);
            #pragma unroll
            for (int rh = 0; rh < 2; rh++)
                #pragma unroll
                for (int d = 0; d < 2; d++){
                    int m = m0 + wm + g + 8*rh;
                    int j = j0 + 2*t + d;
                    int q = rh*2 + d;
                    float r = sigf(acc[0][0][q] + b_ih1[j] + acc[0][3][q] + b_hh1[j]);
                    float z = sigf(acc[0][1][q] + b_ih1[HH+j] + acc[0][4][q] + b_hh1[HH+j]);
                    float nn = tanhf(acc[0][2][q] + b_ih1[2*HH+j]
                                     + r * (acc[0][5][q] + b_hh1[2*HH+j]));
                    float hnew = (1.f - z) * nn + z * __ldcg(&g_hp[m*HH + j]);
                    g_h[m*HH + j] = hnew;
                    bf hi = __float2bfloat16(hnew);
                    g_h_hi[m*HH + j] = hi;
                    g_h_lo[m*HH + j] = __float2bfloat16(hnew - __bfloat162float(hi));
                    hid_o[((size_t)m*TT + ts)*HH + j] = hnew;
                }
        }
        grid_barrier(target);
    }

    // tail: est(h_final) -> out_o[:, T-1, :] ; h_final copy
    for (int idx = gtid; idx < BB*DD; idx += gs){
        int b = idx >> 7, d = idx & 127;
        const float4* hv = (const float4*)(g_h + (size_t)b*HH);
        const float4* wv = (const float4*)(W_out + (size_t)d*HH);
        float s = b_out[d];
        #pragma unroll 8
        for (int q = 0; q < HH/4; q++){
            float4 a = __ldcg(&hv[q]); float4 w = __ldg(&wv[q]);
            s += a.x*w.x + a.y*w.y + a.z*w.z + a.w*w.w;
        }
        out_o[((size_t)b*TT + (TT-1))*DD + d] = s;
    }
    for (int idx = gtid; idx < BB*HH; idx += gs)
        hf_o[idx] = __ldcg(&g_h[idx]);
}

extern "C" void kernel_launch(void* const* d_in, const int* in_sizes, int n_in,
                              void* d_out, int out_size) {
    const float* X     = (const float*)d_in[0];
    const float* Msk   = (const float*)d_in[1];
    const float* W_ih0 = (const float*)d_in[2];
    const float* W_hh0 = (const float*)d_in[3];
    const float* b_ih0 = (const float*)d_in[4];
    const float* b_hh0 = (const float*)d_in[5];
    const float* W_ih1 = (const float*)d_in[6];
    const float* W_hh1 = (const float*)d_in[7];
    const float* b_ih1 = (const float*)d_in[8];
    const float* b_hh1 = (const float*)d_in[9];
    const float* W_out = (const float*)d_in[10];
    const float* b_out = (const float*)d_in[11];

    static bool attr_set = false;
    if (!attr_set){
        cudaFuncSetAttribute(brits_kernel, cudaFuncAttributeMaxDynamicSharedMemorySize, SMEMSZ);
        attr_set = true;
    }
    init_kernel<<<512, 256>>>(W_ih0, W_hh0, W_ih1, W_hh1, W_out);
    brits_kernel<<<NCTA, 256, SMEMSZ>>>(X, Msk, b_ih0, b_hh0, b_ih1, b_hh1,
                                        W_out, b_out, (float*)d_out);
}